// round 8
// baseline (speedup 1.0000x reference)
#include <cuda_runtime.h>
#include <cuda_fp16.h>

#define D128 128
#define MAXN 50000
#define BK 32

// ---------------- scratch (device globals; no allocation allowed) ----------------
__device__ __align__(16) float  g_H1n[MAXN * D128];  // relu(LN(x@node_w1+b1))
__device__ __align__(16) __half g_A[MAXN * D128];    // x @ W_src   (fp16)
__device__ __align__(16) __half g_B[MAXN * D128];    // x @ W_dst   (fp16)
__device__ __align__(16) float  g_S[MAXN * D128];    // segment_sum of edge v
__device__ __align__(16) float  g_T[MAXN * D128];    // H1n @ Wnc
__device__ __align__(16) float  g_deg[MAXN];
__device__ __align__(16) float  g_rsA[MAXN];         // rowsum of g_A (fp16-rounded)
__device__ __align__(16) float  g_rsB[MAXN];         // rowsum of g_B
__device__ __align__(16) float  g_Wnc[D128 * D128];
__device__ __align__(16) float  g_Wec[D128 * D128];
__device__ __align__(16) float  g_cbias[D128];
__device__ __align__(16) float  g_evec[D128];
__device__ __align__(16) float  g_w5s[8];            // colsums of W5 [0..4], sum(eb1) [5]
__device__ int g_idx64;

// ---------------- packed fp32x2 helpers (sm_103a FFMA2 path) ----------------
static __device__ __forceinline__ unsigned long long pack2(float x, float y) {
    unsigned long long r;
    asm("mov.b64 %0, {%1,%2};" : "=l"(r) : "f"(x), "f"(y));
    return r;
}
static __device__ __forceinline__ void fma2(unsigned long long& d,
                                            unsigned long long a,
                                            unsigned long long b) {
    asm("fma.rn.f32x2 %0, %1, %2, %0;" : "+l"(d) : "l"(a), "l"(b));
}
static __device__ __forceinline__ float2 unpack2(unsigned long long v) {
    float2 r;
    asm("mov.b64 {%0,%1}, %2;" : "=f"(r.x), "=f"(r.y) : "l"(v));
    return r;
}
static __device__ __forceinline__ unsigned h2u(__half2 h) {
    return *reinterpret_cast<unsigned*>(&h);
}
static __device__ __forceinline__ float2 u2f2(unsigned u) {
    __half2 h = *reinterpret_cast<__half2*>(&u);
    return __half22float2(h);
}

// ---------------- zero S/deg + (block 0) dtype detect + (block 1) W5 colsums ----------------
__global__ void zero_detect_kernel(float4* __restrict__ S4, float* __restrict__ deg,
                                   long long nS4, int N,
                                   const unsigned int* __restrict__ w, int nwords,
                                   const float* __restrict__ W5,
                                   const float* __restrict__ eb1)
{
    __shared__ int any_nonzero;
    __shared__ float red[4][6];

    long long i = (long long)blockIdx.x * blockDim.x + threadIdx.x;
    if (i < nS4) S4[i] = make_float4(0.f, 0.f, 0.f, 0.f);
    long long j = i - nS4;
    if (j >= 0 && j < N) deg[j] = 0.f;

    if (blockIdx.x == 0) {
        if (threadIdx.x == 0) any_nonzero = 0;
        __syncthreads();
        for (int t = threadIdx.x; t < nwords / 2; t += blockDim.x)
            if (w[2 * t + 1] != 0u) any_nonzero = 1;
        __syncthreads();
        if (threadIdx.x == 0) g_idx64 = any_nonzero ? 0 : 1;
    } else if (blockIdx.x == 1) {
        int t = threadIdx.x;
        if (t < 128) {
            float v[6];
            #pragma unroll
            for (int k = 0; k < 5; k++) v[k] = W5[k * 128 + t];
            v[5] = eb1[t];
            #pragma unroll
            for (int k = 0; k < 6; k++) {
                float s = v[k];
                #pragma unroll
                for (int o = 16; o; o >>= 1) s += __shfl_xor_sync(0xffffffffu, s, o);
                v[k] = s;
            }
            if ((t & 31) == 0) {
                #pragma unroll
                for (int k = 0; k < 6; k++) red[t >> 5][k] = v[k];
            }
        }
        __syncthreads();
        if (t < 6) g_w5s[t] = red[0][t] + red[1][t] + red[2][t] + red[3][t];
    }
}

// ---------------- shared GEMM inner pass ----------------
__device__ __forceinline__ void gemm_pass(
    const float* __restrict__ X, const float* __restrict__ W,
    int n0, int N, int tid, int tx, int ty,
    float* Xs2, float* Ws, unsigned long long (&acc)[8][4])
{
    for (int kk = 0; kk < 128; kk += BK) {
        __syncthreads();
        #pragma unroll
        for (int i = 0; i < 4; i++) {
            int idx = tid + i * 256;
            int row = idx >> 3, q = idx & 7;
            int gr = n0 + row; if (gr > N - 1) gr = N - 1;
            float4 v = *(const float4*)(X + (size_t)gr * 128 + kk + q * 4);
            float* s = Xs2 + row * 64 + q * 8;
            *(float4*)(s)     = make_float4(v.x, v.x, v.y, v.y);
            *(float4*)(s + 4) = make_float4(v.z, v.z, v.w, v.w);
        }
        #pragma unroll
        for (int i = 0; i < 4; i++) {
            int idx = tid + i * 256;
            int kr = idx >> 5, cq = idx & 31;
            float4 v = *(const float4*)(W + (size_t)(kk + kr) * 128 + cq * 4);
            *(float4*)(Ws + kr * 128 + cq * 4) = v;
        }
        __syncthreads();
        #pragma unroll
        for (int k = 0; k < BK; k++) {
            float4 b0 = *(const float4*)(Ws + k * 128 + tx * 4);
            float4 b1 = *(const float4*)(Ws + k * 128 + 64 + tx * 4);
            unsigned long long bp[4];
            bp[0] = pack2(b0.x, b0.y); bp[1] = pack2(b0.z, b0.w);
            bp[2] = pack2(b1.x, b1.y); bp[3] = pack2(b1.z, b1.w);
            #pragma unroll
            for (int i = 0; i < 8; i++) {
                int row = (i < 4) ? (ty * 4 + i) : (64 + ty * 4 + (i - 4));
                unsigned long long a2 =
                    *(const unsigned long long*)(Xs2 + row * 64 + k * 2);
                fma2(acc[i][0], a2, bp[0]);
                fma2(acc[i][1], a2, bp[1]);
                fma2(acc[i][2], a2, bp[2]);
                fma2(acc[i][3], a2, bp[3]);
            }
        }
    }
}

// ---------------- fused N/A/B GEMM ----------------
__global__ __launch_bounds__(256, 2) void gemm_nab_kernel(
    const float* __restrict__ X,
    const float* __restrict__ node_w1, const float* __restrict__ edge_w1,
    const float* __restrict__ bias, const float* __restrict__ g,
    const float* __restrict__ be,
    float* __restrict__ H, __half* __restrict__ A, __half* __restrict__ B,
    float* __restrict__ rsA, float* __restrict__ rsB,
    int N, int ybase)
{
    __shared__ float Xs2[128 * 64];
    __shared__ float Ws[BK * 128];
    int tid = threadIdx.x, tx = tid & 15, ty = tid >> 4;
    int n0 = blockIdx.x * 128;
    int y = blockIdx.y + ybase;
    const float* W = (y == 0) ? node_w1 : (y == 1 ? edge_w1 : edge_w1 + 128 * 128);

    unsigned long long acc[8][4];
    #pragma unroll
    for (int i = 0; i < 8; i++)
        #pragma unroll
        for (int p = 0; p < 4; p++) acc[i][p] = 0ULL;

    gemm_pass(X, W, n0, N, tid, tx, ty, Xs2, Ws, acc);

    if (y == 0) {
        float4 bi0 = *(const float4*)(bias + tx * 4);
        float4 bi1 = *(const float4*)(bias + 64 + tx * 4);
        float4 gg0 = *(const float4*)(g + tx * 4);
        float4 gg1 = *(const float4*)(g + 64 + tx * 4);
        float4 ee0 = *(const float4*)(be + tx * 4);
        float4 ee1 = *(const float4*)(be + 64 + tx * 4);
        #pragma unroll
        for (int i = 0; i < 8; i++) {
            int row = (i < 4) ? (ty * 4 + i) : (64 + ty * 4 + (i - 4));
            int gr = n0 + row;
            float2 f0 = unpack2(acc[i][0]), f1 = unpack2(acc[i][1]);
            float2 f2 = unpack2(acc[i][2]), f3 = unpack2(acc[i][3]);
            float v[8] = { f0.x + bi0.x, f0.y + bi0.y, f1.x + bi0.z, f1.y + bi0.w,
                           f2.x + bi1.x, f2.y + bi1.y, f3.x + bi1.z, f3.y + bi1.w };
            float s = 0.f, ss = 0.f;
            #pragma unroll
            for (int j = 0; j < 8; j++) { s += v[j]; ss += v[j] * v[j]; }
            #pragma unroll
            for (int o = 8; o; o >>= 1) {
                s  += __shfl_xor_sync(0xffffffffu, s,  o);
                ss += __shfl_xor_sync(0xffffffffu, ss, o);
            }
            float mean = s * (1.0f / 128.0f);
            float var  = ss * (1.0f / 128.0f) - mean * mean;
            float rs   = rsqrtf(var + 1e-5f);
            float o0 = fmaxf(0.f, (v[0] - mean) * rs * gg0.x + ee0.x);
            float o1 = fmaxf(0.f, (v[1] - mean) * rs * gg0.y + ee0.y);
            float o2 = fmaxf(0.f, (v[2] - mean) * rs * gg0.z + ee0.z);
            float o3 = fmaxf(0.f, (v[3] - mean) * rs * gg0.w + ee0.w);
            float o4 = fmaxf(0.f, (v[4] - mean) * rs * gg1.x + ee1.x);
            float o5 = fmaxf(0.f, (v[5] - mean) * rs * gg1.y + ee1.y);
            float o6 = fmaxf(0.f, (v[6] - mean) * rs * gg1.z + ee1.z);
            float o7 = fmaxf(0.f, (v[7] - mean) * rs * gg1.w + ee1.w);
            if (gr < N) {
                *(float4*)(H + (size_t)gr * 128 + tx * 4)      = make_float4(o0, o1, o2, o3);
                *(float4*)(H + (size_t)gr * 128 + 64 + tx * 4) = make_float4(o4, o5, o6, o7);
            }
        }
    } else {
        __half* Yh = (y == 1) ? A : B;
        float* rs  = (y == 1) ? rsA : rsB;
        #pragma unroll
        for (int i = 0; i < 8; i++) {
            int row = (i < 4) ? (ty * 4 + i) : (64 + ty * 4 + (i - 4));
            int gr = n0 + row;
            float2 f0 = unpack2(acc[i][0]), f1 = unpack2(acc[i][1]);
            float2 f2 = unpack2(acc[i][2]), f3 = unpack2(acc[i][3]);
            uint2 u0, u1;
            u0.x = h2u(__floats2half2_rn(f0.x, f0.y));
            u0.y = h2u(__floats2half2_rn(f1.x, f1.y));
            u1.x = h2u(__floats2half2_rn(f2.x, f2.y));
            u1.y = h2u(__floats2half2_rn(f3.x, f3.y));
            // rowsum of the fp16-ROUNDED values (matches what edge kernel will read)
            float2 r0 = u2f2(u0.x), r1 = u2f2(u0.y), r2 = u2f2(u1.x), r3 = u2f2(u1.y);
            float part = r0.x + r0.y + r1.x + r1.y + r2.x + r2.y + r3.x + r3.y;
            #pragma unroll
            for (int o = 1; o <= 8; o <<= 1)
                part += __shfl_xor_sync(0xffffffffu, part, o);
            if (gr < N) {
                *(uint2*)(Yh + (size_t)gr * 128 + tx * 4)      = u0;
                *(uint2*)(Yh + (size_t)gr * 128 + 64 + tx * 4) = u1;
                if (tx == 0) rs[gr] = part;
            }
        }
    }
}

// ---------------- T = H @ Wnc ----------------
__global__ __launch_bounds__(256, 2) void gemm_t_kernel(
    const float* __restrict__ H, float* __restrict__ T, int N)
{
    __shared__ float Xs2[128 * 64];
    __shared__ float Ws[BK * 128];
    int tid = threadIdx.x, tx = tid & 15, ty = tid >> 4;
    int n0 = blockIdx.x * 128;
    unsigned long long acc[8][4];
    #pragma unroll
    for (int i = 0; i < 8; i++)
        #pragma unroll
        for (int p = 0; p < 4; p++) acc[i][p] = 0ULL;

    gemm_pass(H, g_Wnc, n0, N, tid, tx, ty, Xs2, Ws, acc);

    #pragma unroll
    for (int i = 0; i < 8; i++) {
        int row = (i < 4) ? (ty * 4 + i) : (64 + ty * 4 + (i - 4));
        int gr = n0 + row;
        if (gr < N) {
            float2 f0 = unpack2(acc[i][0]), f1 = unpack2(acc[i][1]);
            float2 f2 = unpack2(acc[i][2]), f3 = unpack2(acc[i][3]);
            *(float4*)(T + (size_t)gr * 128 + tx * 4)      = make_float4(f0.x, f0.y, f1.x, f1.y);
            *(float4*)(T + (size_t)gr * 128 + 64 + tx * 4) = make_float4(f2.x, f2.y, f3.x, f3.y);
        }
    }
}

// ---------------- final: out = LN(T + S@Wec + x + cbias + deg*evec) ----------------
__global__ __launch_bounds__(256, 2) void final_kernel(
    const float* __restrict__ T, const float* __restrict__ S,
    const float* __restrict__ x, const float* __restrict__ deg,
    const float* __restrict__ lng, const float* __restrict__ lnb,
    float* __restrict__ Y, int N)
{
    __shared__ float Xs2[128 * 64];
    __shared__ float Ws[BK * 128];
    int tid = threadIdx.x, tx = tid & 15, ty = tid >> 4;
    int n0 = blockIdx.x * 128;
    unsigned long long acc[8][4];
    #pragma unroll
    for (int i = 0; i < 8; i++)
        #pragma unroll
        for (int p = 0; p < 4; p++) acc[i][p] = 0ULL;

    gemm_pass(S, g_Wec, n0, N, tid, tx, ty, Xs2, Ws, acc);

    float4 cb0 = *(const float4*)(g_cbias + tx * 4);
    float4 cb1 = *(const float4*)(g_cbias + 64 + tx * 4);
    float4 ev0 = *(const float4*)(g_evec + tx * 4);
    float4 ev1 = *(const float4*)(g_evec + 64 + tx * 4);
    float4 gg0 = *(const float4*)(lng + tx * 4);
    float4 gg1 = *(const float4*)(lng + 64 + tx * 4);
    float4 bb0 = *(const float4*)(lnb + tx * 4);
    float4 bb1 = *(const float4*)(lnb + 64 + tx * 4);

    #pragma unroll
    for (int i = 0; i < 8; i++) {
        int row = (i < 4) ? (ty * 4 + i) : (64 + ty * 4 + (i - 4));
        int gr = n0 + row;
        int gl = (gr > N - 1) ? (N - 1) : gr;
        float d = deg[gl];
        float4 xr0 = *(const float4*)(x + (size_t)gl * 128 + tx * 4);
        float4 xr1 = *(const float4*)(x + (size_t)gl * 128 + 64 + tx * 4);
        float4 tr0 = *(const float4*)(T + (size_t)gl * 128 + tx * 4);
        float4 tr1 = *(const float4*)(T + (size_t)gl * 128 + 64 + tx * 4);
        float2 f0 = unpack2(acc[i][0]), f1 = unpack2(acc[i][1]);
        float2 f2 = unpack2(acc[i][2]), f3 = unpack2(acc[i][3]);
        float v[8];
        v[0] = f0.x + tr0.x + xr0.x + cb0.x + d * ev0.x;
        v[1] = f0.y + tr0.y + xr0.y + cb0.y + d * ev0.y;
        v[2] = f1.x + tr0.z + xr0.z + cb0.z + d * ev0.z;
        v[3] = f1.y + tr0.w + xr0.w + cb0.w + d * ev0.w;
        v[4] = f2.x + tr1.x + xr1.x + cb1.x + d * ev1.x;
        v[5] = f2.y + tr1.y + xr1.y + cb1.y + d * ev1.y;
        v[6] = f3.x + tr1.z + xr1.z + cb1.z + d * ev1.z;
        v[7] = f3.y + tr1.w + xr1.w + cb1.w + d * ev1.w;
        float s = 0.f, ss = 0.f;
        #pragma unroll
        for (int j = 0; j < 8; j++) { s += v[j]; ss += v[j] * v[j]; }
        #pragma unroll
        for (int o = 8; o; o >>= 1) {
            s  += __shfl_xor_sync(0xffffffffu, s,  o);
            ss += __shfl_xor_sync(0xffffffffu, ss, o);
        }
        float mean = s * (1.0f / 128.0f);
        float var  = ss * (1.0f / 128.0f) - mean * mean;
        float rs   = rsqrtf(var + 1e-5f);
        float o0 = (v[0] - mean) * rs * gg0.x + bb0.x;
        float o1 = (v[1] - mean) * rs * gg0.y + bb0.y;
        float o2 = (v[2] - mean) * rs * gg0.z + bb0.z;
        float o3 = (v[3] - mean) * rs * gg0.w + bb0.w;
        float o4 = (v[4] - mean) * rs * gg1.x + bb1.x;
        float o5 = (v[5] - mean) * rs * gg1.y + bb1.y;
        float o6 = (v[6] - mean) * rs * gg1.z + bb1.z;
        float o7 = (v[7] - mean) * rs * gg1.w + bb1.w;
        if (gr < N) {
            *(float4*)(Y + (size_t)gr * 128 + tx * 4)      = make_float4(o0, o1, o2, o3);
            *(float4*)(Y + (size_t)gr * 128 + 64 + tx * 4) = make_float4(o4, o5, o6, o7);
        }
    }
}

// ---------------- edge kernel: persistent, ILP-2, mean via precomputed rowsums ----------------
__global__ __launch_bounds__(256, 4) void edge_kernel(
    const __half* __restrict__ A, const __half* __restrict__ B,
    const float* __restrict__ rsA, const float* __restrict__ rsB,
    const float* __restrict__ ea, const void* __restrict__ ei_raw,
    const float* __restrict__ W5, const float* __restrict__ eb1,
    const float* __restrict__ g1, const float* __restrict__ be1,
    float* __restrict__ S, float* __restrict__ deg, int E, int N)
{
    __shared__ float sW5[5 * 128];
    __shared__ float sb[128], sg[128], sbe[128];
    int tid = threadIdx.x;
    for (int i = tid; i < 5 * 128; i += 256) sW5[i] = W5[i];
    if (tid < 128) { sb[tid] = eb1[tid]; sg[tid] = g1[tid]; sbe[tid] = be1[tid]; }
    __syncthreads();

    int lane = tid & 31;
    int gw = (blockIdx.x * 256 + tid) >> 5;
    int nw = (gridDim.x * 256) >> 5;
    int idx64 = g_idx64;
    int c = lane * 4;

    float4 w0 = *(const float4*)(sW5 + 0 * 128 + c);
    float4 w1 = *(const float4*)(sW5 + 1 * 128 + c);
    float4 w2 = *(const float4*)(sW5 + 2 * 128 + c);
    float4 w3 = *(const float4*)(sW5 + 3 * 128 + c);
    float4 w4 = *(const float4*)(sW5 + 4 * 128 + c);
    float4 sb4 = *(const float4*)(sb + c);
    float4 sg4 = *(const float4*)(sg + c);
    float4 se4 = *(const float4*)(sbe + c);
    // colsum constants for mean computation
    float w5s0 = g_w5s[0], w5s1 = g_w5s[1], w5s2 = g_w5s[2];
    float w5s3 = g_w5s[3], w5s4 = g_w5s[4], b1sum = g_w5s[5];

    for (long long e0 = 2LL * gw; e0 < E; e0 += 2LL * nw) {
        long long e1 = e0 + 1;
        bool valid1 = (e1 < E);

        int src0, dst0, src1, dst1;
        if (idx64) {
            const long long* ei = (const long long*)ei_raw;
            src0 = (int)ei[e0];
            dst0 = (int)ei[(long long)E + e0];
            src1 = valid1 ? (int)ei[e1] : src0;
            dst1 = valid1 ? (int)ei[(long long)E + e1] : dst0;
        } else {
            const int* ei = (const int*)ei_raw;
            src0 = ei[e0];
            dst0 = ei[(long long)E + e0];
            src1 = valid1 ? ei[e1] : src0;
            dst1 = valid1 ? ei[(long long)E + e1] : dst0;
        }
        src0 = min(max(src0, 0), N - 1); dst0 = min(max(dst0, 0), N - 1);
        src1 = min(max(src1, 0), N - 1); dst1 = min(max(dst1, 0), N - 1);

        uint2 ra0 = __ldg((const uint2*)(A + (size_t)src0 * 128 + c));
        uint2 rb0 = __ldg((const uint2*)(B + (size_t)dst0 * 128 + c));
        uint2 ra1 = __ldg((const uint2*)(A + (size_t)src1 * 128 + c));
        uint2 rb1 = __ldg((const uint2*)(B + (size_t)dst1 * 128 + c));

        float rsa0 = __ldg(rsA + src0), rsb0 = __ldg(rsB + dst0);
        float rsa1 = __ldg(rsA + src1), rsb1 = __ldg(rsB + dst1);

        const float* eap0 = ea + e0 * 5;
        const float* eap1 = ea + e1 * 5;
        float e00 = eap0[0], e01 = eap0[1], e02 = eap0[2], e03 = eap0[3], e04 = eap0[4];
        float e10, e11, e12, e13, e14;
        if (valid1) { e10 = eap1[0]; e11 = eap1[1]; e12 = eap1[2]; e13 = eap1[3]; e14 = eap1[4]; }
        else        { e10 = e00; e11 = e01; e12 = e02; e13 = e03; e14 = e04; }

        float2 a0lo = u2f2(ra0.x), a0hi = u2f2(ra0.y);
        float2 b0lo = u2f2(rb0.x), b0hi = u2f2(rb0.y);
        float2 a1lo = u2f2(ra1.x), a1hi = u2f2(ra1.y);
        float2 b1lo = u2f2(rb1.x), b1hi = u2f2(rb1.y);

        float base0 = sb4.x + e00 * w0.x + e01 * w1.x + e02 * w2.x + e03 * w3.x + e04 * w4.x;
        float base1 = sb4.y + e00 * w0.y + e01 * w1.y + e02 * w2.y + e03 * w3.y + e04 * w4.y;
        float base2 = sb4.z + e00 * w0.z + e01 * w1.z + e02 * w2.z + e03 * w3.z + e04 * w4.z;
        float base3 = sb4.w + e00 * w0.w + e01 * w1.w + e02 * w2.w + e03 * w3.w + e04 * w4.w;
        float p00 = a0lo.x + b0lo.x + base0;
        float p01 = a0lo.y + b0lo.y + base1;
        float p02 = a0hi.x + b0hi.x + base2;
        float p03 = a0hi.y + b0hi.y + base3;

        float c0 = sb4.x + e10 * w0.x + e11 * w1.x + e12 * w2.x + e13 * w3.x + e14 * w4.x;
        float c1 = sb4.y + e10 * w0.y + e11 * w1.y + e12 * w2.y + e13 * w3.y + e14 * w4.y;
        float c2 = sb4.z + e10 * w0.z + e11 * w1.z + e12 * w2.z + e13 * w3.z + e14 * w4.z;
        float c3 = sb4.w + e10 * w0.w + e11 * w1.w + e12 * w2.w + e13 * w3.w + e14 * w4.w;
        float p10 = a1lo.x + b1lo.x + c0;
        float p11 = a1lo.y + b1lo.y + c1;
        float p12 = a1hi.x + b1hi.x + c2;
        float p13 = a1hi.y + b1hi.y + c3;

        // mean from precomputed sums (no butterfly)
        float sum0 = rsa0 + rsb0 + b1sum
                   + e00 * w5s0 + e01 * w5s1 + e02 * w5s2 + e03 * w5s3 + e04 * w5s4;
        float sum1 = rsa1 + rsb1 + b1sum
                   + e10 * w5s0 + e11 * w5s1 + e12 * w5s2 + e13 * w5s3 + e14 * w5s4;
        float mean0 = sum0 * (1.0f / 128.0f);
        float mean1 = sum1 * (1.0f / 128.0f);

        // variance butterflies (the only remaining warp reductions)
        float q0 = p00 * p00 + p01 * p01 + p02 * p02 + p03 * p03;
        float q1 = p10 * p10 + p11 * p11 + p12 * p12 + p13 * p13;
        #pragma unroll
        for (int o = 16; o; o >>= 1) {
            q0 += __shfl_xor_sync(0xffffffffu, q0, o);
            q1 += __shfl_xor_sync(0xffffffffu, q1, o);
        }
        float rs0 = rsqrtf(q0 * (1.0f / 128.0f) - mean0 * mean0 + 1e-5f);
        float rs1 = rsqrtf(q1 * (1.0f / 128.0f) - mean1 * mean1 + 1e-5f);

        float v00 = fmaxf(0.f, (p00 - mean0) * rs0 * sg4.x + se4.x);
        float v01 = fmaxf(0.f, (p01 - mean0) * rs0 * sg4.y + se4.y);
        float v02 = fmaxf(0.f, (p02 - mean0) * rs0 * sg4.z + se4.z);
        float v03 = fmaxf(0.f, (p03 - mean0) * rs0 * sg4.w + se4.w);

        float* dp0 = S + (size_t)dst0 * 128 + c;
        asm volatile("red.global.add.v4.f32 [%0], {%1,%2,%3,%4};"
                     :: "l"(dp0), "f"(v00), "f"(v01), "f"(v02), "f"(v03) : "memory");

        if (valid1) {
            float v10 = fmaxf(0.f, (p10 - mean1) * rs1 * sg4.x + se4.x);
            float v11 = fmaxf(0.f, (p11 - mean1) * rs1 * sg4.y + se4.y);
            float v12 = fmaxf(0.f, (p12 - mean1) * rs1 * sg4.z + se4.z);
            float v13 = fmaxf(0.f, (p13 - mean1) * rs1 * sg4.w + se4.w);
            float* dp1 = S + (size_t)dst1 * 128 + c;
            asm volatile("red.global.add.v4.f32 [%0], {%1,%2,%3,%4};"
                         :: "l"(dp1), "f"(v10), "f"(v11), "f"(v12), "f"(v13) : "memory");
        }
        if (lane == 0) atomicAdd(deg + dst0, 1.0f);
        if (lane == 1 && valid1) atomicAdd(deg + dst1, 1.0f);
    }
}

// ---------------- prep kernel ----------------
__global__ __launch_bounds__(256, 2) void prep_kernel(
    const float* __restrict__ w2n, const float* __restrict__ w2e,
    const float* __restrict__ U,
    const float* __restrict__ bn2, const float* __restrict__ be2,
    const float* __restrict__ ub,
    float* __restrict__ Wnc, float* __restrict__ Wec,
    float* __restrict__ cb, float* __restrict__ ev)
{
    __shared__ float Xs2[128 * 64];
    __shared__ float Ws[BK * 128];
    int tid = threadIdx.x, tx = tid & 15, ty = tid >> 4;
    int y = blockIdx.y;

    if (y == 2) {
        int j = tid & 127, h = tid >> 7;
        float a = 0.f, b = 0.f;
        int m0 = h * 64;
        #pragma unroll 16
        for (int m = m0; m < m0 + 64; m++) {
            a += bn2[m] * U[m * 128 + j];
            b += be2[m] * U[(128 + m) * 128 + j];
        }
        Xs2[tid] = a;
        Xs2[512 + tid] = b;
        __syncthreads();
        if (h == 0) {
            cb[j] = Xs2[j] + Xs2[128 + j] + ub[j];
            ev[j] = Xs2[512 + j] + Xs2[640 + j];
        }
        return;
    }

    const float* X = y ? w2e : w2n;
    const float* W = y ? (U + 128 * 128) : U;
    float* out = y ? Wec : Wnc;

    unsigned long long acc[8][4];
    #pragma unroll
    for (int i = 0; i < 8; i++)
        #pragma unroll
        for (int p = 0; p < 4; p++) acc[i][p] = 0ULL;

    gemm_pass(X, W, 0, 128, tid, tx, ty, Xs2, Ws, acc);

    #pragma unroll
    for (int i = 0; i < 8; i++) {
        int row = (i < 4) ? (ty * 4 + i) : (64 + ty * 4 + (i - 4));
        float2 f0 = unpack2(acc[i][0]), f1 = unpack2(acc[i][1]);
        float2 f2 = unpack2(acc[i][2]), f3 = unpack2(acc[i][3]);
        *(float4*)(out + (size_t)row * 128 + tx * 4)      = make_float4(f0.x, f0.y, f1.x, f1.y);
        *(float4*)(out + (size_t)row * 128 + 64 + tx * 4) = make_float4(f2.x, f2.y, f3.x, f3.y);
    }
}

// ---------------- launch ----------------
extern "C" void kernel_launch(void* const* d_in, const int* in_sizes, int n_in,
                              void* d_out, int out_size)
{
    const float* x         = (const float*)d_in[0];
    const float* edge_attr = (const float*)d_in[1];
    const float* node_w1   = (const float*)d_in[3];
    const float* node_b1   = (const float*)d_in[4];
    const float* node_g1   = (const float*)d_in[5];
    const float* node_be1  = (const float*)d_in[6];
    const float* node_w2   = (const float*)d_in[7];
    const float* node_b2   = (const float*)d_in[8];
    const float* edge_w1   = (const float*)d_in[9];
    const float* edge_b1   = (const float*)d_in[10];
    const float* edge_g1   = (const float*)d_in[11];
    const float* edge_be1  = (const float*)d_in[12];
    const float* edge_w2   = (const float*)d_in[13];
    const float* edge_b2   = (const float*)d_in[14];
    const float* upd_w     = (const float*)d_in[15];
    const float* upd_b     = (const float*)d_in[16];
    const float* ln_g      = (const float*)d_in[17];
    const float* ln_b      = (const float*)d_in[18];
    const void*  ei        = d_in[19];
    float* out = (float*)d_out;

    int N = in_sizes[0] / 128;
    int E = in_sizes[19] / 2;

    float *pH, *pS, *pT, *pdeg, *pWnc, *pWec, *pcb, *pev, *prsA, *prsB;
    __half *pA, *pB;
    cudaGetSymbolAddress((void**)&pH,   g_H1n);
    cudaGetSymbolAddress((void**)&pA,   g_A);
    cudaGetSymbolAddress((void**)&pB,   g_B);
    cudaGetSymbolAddress((void**)&pS,   g_S);
    cudaGetSymbolAddress((void**)&pT,   g_T);
    cudaGetSymbolAddress((void**)&pdeg, g_deg);
    cudaGetSymbolAddress((void**)&prsA, g_rsA);
    cudaGetSymbolAddress((void**)&prsB, g_rsB);
    cudaGetSymbolAddress((void**)&pWnc, g_Wnc);
    cudaGetSymbolAddress((void**)&pWec, g_Wec);
    cudaGetSymbolAddress((void**)&pcb,  g_cbias);
    cudaGetSymbolAddress((void**)&pev,  g_evec);

    static cudaStream_t s1 = 0;
    static cudaEvent_t eFork = 0, eZero = 0, eJoin = 0;
    if (!s1) cudaStreamCreateWithFlags(&s1, cudaStreamNonBlocking);
    if (!eFork) cudaEventCreateWithFlags(&eFork, cudaEventDisableTiming);
    if (!eZero) cudaEventCreateWithFlags(&eZero, cudaEventDisableTiming);
    if (!eJoin) cudaEventCreateWithFlags(&eJoin, cudaEventDisableTiming);

    cudaStream_t s0 = cudaStreamLegacy;
    {
        cudaStreamCaptureStatus st = cudaStreamCaptureStatusNone;
        if (cudaStreamIsCapturing(cudaStreamLegacy, &st) == cudaSuccess &&
            st == cudaStreamCaptureStatusActive) {
            s0 = cudaStreamLegacy;
        } else {
            cudaStreamCaptureStatus st2 = cudaStreamCaptureStatusNone;
            if (cudaStreamIsCapturing(cudaStreamPerThread, &st2) == cudaSuccess &&
                st2 == cudaStreamCaptureStatusActive) {
                s0 = cudaStreamPerThread;
            }
        }
    }

    int gb = (N + 127) / 128;
    int nwords = 2 * E; if (nwords > 1024) nwords = 1024;
    long long nS4 = (long long)N * 32;
    long long ztot = nS4 + N;

    // fork
    cudaEventRecord(eFork, s0);
    cudaStreamWaitEvent(s1, eFork, 0);

    // s0 #1: A,B GEMMs (+ rowsums) start immediately (critical path head)
    gemm_nab_kernel<<<dim3(gb, 2), 256, 0, s0>>>(x, node_w1, edge_w1,
                                                 node_b1, node_g1, node_be1,
                                                 pH, pA, pB, prsA, prsB, N, /*ybase=*/1);

    // s1 #2: zero S/deg + dtype detect + W5 colsums (off critical path)
    zero_detect_kernel<<<(unsigned)((ztot + 255) / 256), 256, 0, s1>>>(
        (float4*)pS, pdeg, nS4, N, (const unsigned int*)ei, nwords,
        edge_w1 + 256 * 128, edge_b1);
    cudaEventRecord(eZero, s1);

    // s1 #3: prep
    prep_kernel<<<dim3(1, 3), 256, 0, s1>>>(node_w2, edge_w2, upd_w,
                                            node_b2, edge_b2, upd_b,
                                            pWnc, pWec, pcb, pev);

    // s0 #4: edge pipeline (needs zero + colsums done)
    cudaStreamWaitEvent(s0, eZero, 0);
    edge_kernel<<<592, 256, 0, s0>>>(pA, pB, prsA, prsB, edge_attr, ei,
                                     edge_w1 + 256 * 128, edge_b1, edge_g1, edge_be1,
                                     pS, pdeg, E, N);

    // s1 #5: H GEMM
    gemm_nab_kernel<<<dim3(gb, 1), 256, 0, s1>>>(x, node_w1, edge_w1,
                                                 node_b1, node_g1, node_be1,
                                                 pH, pA, pB, prsA, prsB, N, /*ybase=*/0);

    // s1 #6: T = H @ Wnc
    gemm_t_kernel<<<gb, 256, 0, s1>>>(pH, pT, N);

    // join
    cudaEventRecord(eJoin, s1);
    cudaStreamWaitEvent(s0, eJoin, 0);

    // s0 #7: final
    final_kernel<<<gb, 256, 0, s0>>>(pT, pS, x, pdeg, ln_g, ln_b, out, N);
}